// round 1
// baseline (speedup 1.0000x reference)
#include <cuda_runtime.h>
#include <cstddef>

#define NB 32
#define NN 1024
#define NF 64
#define NO 128

// Scratch for pairwise sums (device globals: no allocation at runtime)
__device__ float g_wsum[NB * NN];
__device__ float g_dwsum[NB * NN];

__device__ __forceinline__ float fast_exp2(float t) {
    float r;
    asm("ex2.approx.f32 %0, %1;" : "=f"(r) : "f"(t));
    return r;
}

// ---------------------------------------------------------------------------
// Kernel 1: pairwise Gaussian sums.
// grid = NB * (NN/64) = 512 blocks, 256 threads.
// Each block: one batch, 64 j's. 4 threads per j, each covering 256 i's.
// ---------------------------------------------------------------------------
__global__ void __launch_bounds__(256) pairwise_kernel(const float* __restrict__ x) {
    __shared__ float2 sc[NN];
    __shared__ float red_w[4][64];
    __shared__ float red_d[4][64];

    const int b = blockIdx.x >> 4;            // 16 blocks per batch
    const int jbase = (blockIdx.x & 15) * 64;
    const float* xb = x + (size_t)b * NN * NF;

    // load all coords of this batch (last 2 features of each row)
    for (int idx = threadIdx.x; idx < NN; idx += 256) {
        sc[idx] = *(const float2*)(xb + (size_t)idx * NF + (NF - 2));
    }
    __syncthreads();

    const int jloc = threadIdx.x & 63;
    const int ci = threadIdx.x >> 6;          // i-chunk 0..3
    const int j = jbase + jloc;
    const float jx = sc[j].x, jy = sc[j].y;

    // K = -10 * log2(e): exp(-10*d) = 2^(d*K)
    const float K = -14.4269504089f;

    float ws0 = 0.f, ws1 = 0.f, dw0 = 0.f, dw1 = 0.f;
    const int i0 = ci * 256;

    #pragma unroll 8
    for (int i = i0; i < i0 + 256; i += 2) {
        float2 c0 = sc[i];
        float2 c1 = sc[i + 1];

        float dx0 = c0.x - jx, dy0 = c0.y - jy;
        float d0 = fmaf(dy0, dy0, dx0 * dx0);
        float w0 = fast_exp2(d0 * K);
        ws0 += w0;
        dw0 = fmaf(d0, w0, dw0);

        float dx1 = c1.x - jx, dy1 = c1.y - jy;
        float d1 = fmaf(dy1, dy1, dx1 * dx1);
        float w1 = fast_exp2(d1 * K);
        ws1 += w1;
        dw1 = fmaf(d1, w1, dw1);
    }

    red_w[ci][jloc] = ws0 + ws1;
    red_d[ci][jloc] = dw0 + dw1;
    __syncthreads();

    if (threadIdx.x < 64) {
        int t = threadIdx.x;
        float ws = (red_w[0][t] + red_w[1][t]) + (red_w[2][t] + red_w[3][t]);
        float dw = (red_d[0][t] + red_d[1][t]) + (red_d[2][t] + red_d[3][t]);
        g_wsum[b * NN + jbase + t] = ws;
        g_dwsum[b * NN + jbase + t] = dw;
    }
}

// ---------------------------------------------------------------------------
// Kernel 2: fused GEMM + epilogue.
//   G = x @ [A0 ; A1]   (BN x 64) @ (64 x 256)
//   out[n,c] = (G[n,c] + c1[n]*G[n,c+128] + c2[n]*A2[c] + bias[c]) * m[n]
//   c1 = wsum*m - 1,  c2 = dwsum*m
// grid = BN/32 = 1024 blocks, 256 threads.
// Thread tile: 4 rows x (4 cols of G0 + matching 4 cols of G1).
// Dynamic smem: As[64][256] + Xs[32][64] + A2s[128] + bs[128] (~73 KB).
// ---------------------------------------------------------------------------
__global__ void __launch_bounds__(256) gemm_kernel(
    const float* __restrict__ x,
    const float* __restrict__ mask,
    const float* __restrict__ A,
    const float* __restrict__ bias,
    float* __restrict__ out)
{
    extern __shared__ float smem[];
    float* As = smem;                  // [64][256]
    float* Xs = As + 64 * 256;         // [32][64]
    float* A2s = Xs + 32 * 64;         // [128]
    float* bs = A2s + 128;             // [128]

    const int row0 = blockIdx.x * 32;  // flattened (b*NN + n)

    // Repack A: As[k][c] = A[k][c] for c<128, A[64+k][c-128] for c>=128
    for (int idx = threadIdx.x; idx < 64 * 256; idx += 256) {
        int k = idx >> 8;
        int c = idx & 255;
        As[idx] = (c < 128) ? A[k * 128 + c] : A[(64 + k) * 128 + (c - 128)];
    }
    if (threadIdx.x < 128) {
        A2s[threadIdx.x] = A[128 * 128 + threadIdx.x];
        bs[threadIdx.x] = bias[threadIdx.x];
    }
    // x tile: 32 rows x 64 = 512 float4
    {
        const float4* xg = (const float4*)(x + (size_t)row0 * NF);
        float4* xs4 = (float4*)Xs;
        xs4[threadIdx.x] = xg[threadIdx.x];
        xs4[threadIdx.x + 256] = xg[threadIdx.x + 256];
    }
    __syncthreads();

    const int lane = threadIdx.x & 31;
    const int rg = threadIdx.x >> 5;   // 0..7
    const int r0 = rg * 4;
    const int c0 = lane * 4;           // 0..124

    float acc[4][8];
    #pragma unroll
    for (int r = 0; r < 4; r++)
        #pragma unroll
        for (int j = 0; j < 8; j++)
            acc[r][j] = 0.f;

    #pragma unroll 4
    for (int k = 0; k < 64; k++) {
        float4 a0 = *(const float4*)&As[k * 256 + c0];
        float4 a1 = *(const float4*)&As[k * 256 + c0 + 128];
        #pragma unroll
        for (int r = 0; r < 4; r++) {
            float xv = Xs[(r0 + r) * 64 + k];   // warp-broadcast
            acc[r][0] = fmaf(xv, a0.x, acc[r][0]);
            acc[r][1] = fmaf(xv, a0.y, acc[r][1]);
            acc[r][2] = fmaf(xv, a0.z, acc[r][2]);
            acc[r][3] = fmaf(xv, a0.w, acc[r][3]);
            acc[r][4] = fmaf(xv, a1.x, acc[r][4]);
            acc[r][5] = fmaf(xv, a1.y, acc[r][5]);
            acc[r][6] = fmaf(xv, a1.z, acc[r][6]);
            acc[r][7] = fmaf(xv, a1.w, acc[r][7]);
        }
    }

    #pragma unroll
    for (int r = 0; r < 4; r++) {
        int grow = row0 + r0 + r;
        float m = mask[grow];
        float ws = g_wsum[grow];
        float dw = g_dwsum[grow];
        float c1 = fmaf(ws, m, -1.0f);
        float c2 = dw * m;
        float4 o;
        o.x = (fmaf(c1, acc[r][4], acc[r][0]) + fmaf(c2, A2s[c0 + 0], bs[c0 + 0])) * m;
        o.y = (fmaf(c1, acc[r][5], acc[r][1]) + fmaf(c2, A2s[c0 + 1], bs[c0 + 1])) * m;
        o.z = (fmaf(c1, acc[r][6], acc[r][2]) + fmaf(c2, A2s[c0 + 2], bs[c0 + 2])) * m;
        o.w = (fmaf(c1, acc[r][7], acc[r][3]) + fmaf(c2, A2s[c0 + 3], bs[c0 + 3])) * m;
        *(float4*)&out[(size_t)grow * NO + c0] = o;
    }
}

extern "C" void kernel_launch(void* const* d_in, const int* in_sizes, int n_in,
                              void* d_out, int out_size) {
    const float* x    = (const float*)d_in[0];
    const float* mask = (const float*)d_in[1];
    const float* A    = (const float*)d_in[2];
    const float* bias = (const float*)d_in[3];
    float* out = (float*)d_out;

    const int smem_bytes = (64 * 256 + 32 * 64 + 128 + 128) * sizeof(float);
    cudaFuncSetAttribute(gemm_kernel, cudaFuncAttributeMaxDynamicSharedMemorySize, smem_bytes);

    pairwise_kernel<<<NB * (NN / 64), 256>>>(x);
    gemm_kernel<<<(NB * NN) / 32, 256, smem_bytes>>>(x, mask, A, bias, out);
}

// round 2
// speedup vs baseline: 1.0370x; 1.0370x over previous
#include <cuda_runtime.h>
#include <cstddef>

#define NB 32
#define NN 1024
#define NF 64
#define NO 128
#define GROWS 64   // rows per gemm block

typedef unsigned long long u64;

// Scratch for pairwise sums (device globals: no allocation at runtime)
__device__ float g_wsum[NB * NN];
__device__ float g_dwsum[NB * NN];

__device__ __forceinline__ float fast_exp2(float t) {
    float r;
    asm("ex2.approx.f32 %0, %1;" : "=f"(r) : "f"(t));
    return r;
}

__device__ __forceinline__ u64 pk2(float lo, float hi) {
    u64 r; asm("mov.b64 %0, {%1, %2};" : "=l"(r) : "f"(lo), "f"(hi)); return r;
}
__device__ __forceinline__ void up2(u64 v, float& a, float& b) {
    asm("mov.b64 {%0, %1}, %2;" : "=f"(a), "=f"(b) : "l"(v));
}
#define FMA2ACC(acc, a, b) asm("fma.rn.f32x2 %0, %1, %2, %0;" : "+l"(acc) : "l"(a), "l"(b))
#define FMA2(d, a, b, c)   asm("fma.rn.f32x2 %0, %1, %2, %3;" : "=l"(d) : "l"(a), "l"(b), "l"(c))
#define MUL2(d, a, b)      asm("mul.rn.f32x2 %0, %1, %2;"     : "=l"(d) : "l"(a), "l"(b))
#define ADD2(d, a, b)      asm("add.rn.f32x2 %0, %1, %2;"     : "=l"(d) : "l"(a), "l"(b))

// ---------------------------------------------------------------------------
// Kernel 1: pairwise Gaussian sums, f32x2-packed.
// grid = NB * 16 = 512 blocks, 256 threads.
// Each block: one batch, 64 j's. 4 threads per j, each covering 256 i's.
// ---------------------------------------------------------------------------
__global__ void __launch_bounds__(256) pairwise_kernel(const float* __restrict__ x) {
    __shared__ __align__(16) float2 sc[NN];
    __shared__ float red_w[4][64];
    __shared__ float red_d[4][64];

    const int b = blockIdx.x >> 4;
    const int jbase = (blockIdx.x & 15) * 64;
    const float* xb = x + (size_t)b * NN * NF;

    for (int idx = threadIdx.x; idx < NN; idx += 256) {
        sc[idx] = *(const float2*)(xb + (size_t)idx * NF + (NF - 2));
    }
    __syncthreads();

    const int jloc = threadIdx.x & 63;
    const int ci = threadIdx.x >> 6;
    const float2 cj = sc[jbase + jloc];
    const u64 njp = pk2(-cj.x, -cj.y);                 // (-jx, -jy)
    const float Kc = -14.4269504089f;                  // -10 * log2(e)
    const u64 K2 = pk2(Kc, Kc);

    u64 ws2 = 0ULL, dw2 = 0ULL;                        // packed (0.f, 0.f)
    const int i0 = ci * 256;

    #pragma unroll 4
    for (int i = i0; i < i0 + 256; i += 2) {
        ulonglong2 p = *(const ulonglong2*)&sc[i];     // two float2 coords
        u64 e0; ADD2(e0, p.x, njp);                    // (dx0, dy0)
        u64 e1; ADD2(e1, p.y, njp);
        u64 q0; MUL2(q0, e0, e0);                      // (dx0^2, dy0^2)
        u64 q1; MUL2(q1, e1, e1);
        float q0x, q0y, q1x, q1y;
        up2(q0, q0x, q0y); up2(q1, q1x, q1y);
        float d0 = q0x + q0y;
        float d1 = q1x + q1y;
        u64 dp = pk2(d0, d1);
        u64 tp; MUL2(tp, dp, K2);
        float t0, t1; up2(tp, t0, t1);
        u64 wp = pk2(fast_exp2(t0), fast_exp2(t1));
        ADD2(ws2, ws2, wp);
        FMA2ACC(dw2, dp, wp);
    }

    float wsa, wsb, dwa, dwb;
    up2(ws2, wsa, wsb); up2(dw2, dwa, dwb);
    red_w[ci][jloc] = wsa + wsb;
    red_d[ci][jloc] = dwa + dwb;
    __syncthreads();

    if (threadIdx.x < 64) {
        int t = threadIdx.x;
        g_wsum[b * NN + jbase + t]  = (red_w[0][t] + red_w[1][t]) + (red_w[2][t] + red_w[3][t]);
        g_dwsum[b * NN + jbase + t] = (red_d[0][t] + red_d[1][t]) + (red_d[2][t] + red_d[3][t]);
    }
}

// ---------------------------------------------------------------------------
// Kernel 2: fused GEMM + epilogue, FFMA2 (f32x2) mainloop.
//   G = x @ [A0 ; A1]   (BN x 64) @ (64 x 256)
//   out[n,c] = (G0[n,c] + c1[n]*G1[n,c] + c2[n]*A2[c] + bias[c]) * m[n]
//   c1 = wsum*m - 1,  c2 = dwsum*m
// grid = BN/64 = 512 blocks, 256 threads, 8 warps.
// Thread tile: 8 rows x 4 cols (both G0 and G1 halves) = 8x8 outputs.
// Xs is stored k-major ([64 k][68 rows], padded) so the x operand is a
// broadcast LDS.128 per 4 rows.
// ---------------------------------------------------------------------------
__global__ void __launch_bounds__(256, 2) gemm_kernel(
    const float* __restrict__ x,
    const float* __restrict__ mask,
    const float* __restrict__ A,
    const float* __restrict__ bias,
    float* __restrict__ out)
{
    extern __shared__ float smem[];
    float* As  = smem;                  // [64][256]
    float* Xs  = As + 64 * 256;         // [64 k][68 rows] (padded)
    float* A2s = Xs + 64 * 68;          // [128]
    float* bs  = A2s + 128;             // [128]

    const int row0 = blockIdx.x * GROWS;

    // Repack A: As[k][c] = A0 for c<128, A1 for c>=128
    for (int idx = threadIdx.x; idx < 64 * 256; idx += 256) {
        int k = idx >> 8;
        int c = idx & 255;
        As[idx] = (c < 128) ? A[k * 128 + c] : A[(64 + k) * 128 + (c - 128)];
    }
    if (threadIdx.x < 128) {
        A2s[threadIdx.x] = A[128 * 128 + threadIdx.x];
        bs[threadIdx.x]  = bias[threadIdx.x];
    }
    // x tile transposed into Xs[k][row]
    {
        int row  = threadIdx.x & 63;
        int cseg = threadIdx.x >> 6;          // 0..3 -> 16 features each
        const float* xr = x + (size_t)(row0 + row) * NF + cseg * 16;
        #pragma unroll
        for (int q = 0; q < 4; q++) {
            float4 v = *(const float4*)(xr + q * 4);
            int c = cseg * 16 + q * 4;
            Xs[(c + 0) * 68 + row] = v.x;
            Xs[(c + 1) * 68 + row] = v.y;
            Xs[(c + 2) * 68 + row] = v.z;
            Xs[(c + 3) * 68 + row] = v.w;
        }
    }
    __syncthreads();

    const int lane = threadIdx.x & 31;
    const int rg   = threadIdx.x >> 5;   // warp 0..7
    const int r0   = rg * 8;
    const int c0   = lane * 4;           // 0..124

    u64 acc[8][4];
    #pragma unroll
    for (int r = 0; r < 8; r++)
        #pragma unroll
        for (int j = 0; j < 4; j++)
            acc[r][j] = 0ULL;

    #pragma unroll 8
    for (int k = 0; k < 64; k++) {
        ulonglong2 a0 = *(const ulonglong2*)&As[k * 256 + c0];         // G0 cols c0..c0+3
        ulonglong2 a1 = *(const ulonglong2*)&As[k * 256 + c0 + 128];   // G1 cols
        float4 xva = *(const float4*)&Xs[k * 68 + r0];                 // rows r0..r0+3 (broadcast)
        float4 xvb = *(const float4*)&Xs[k * 68 + r0 + 4];
        float xr8[8] = {xva.x, xva.y, xva.z, xva.w, xvb.x, xvb.y, xvb.z, xvb.w};
        #pragma unroll
        for (int r = 0; r < 8; r++) {
            u64 xx = pk2(xr8[r], xr8[r]);
            FMA2ACC(acc[r][0], xx, a0.x);
            FMA2ACC(acc[r][1], xx, a0.y);
            FMA2ACC(acc[r][2], xx, a1.x);
            FMA2ACC(acc[r][3], xx, a1.y);
        }
    }

    #pragma unroll
    for (int r = 0; r < 8; r++) {
        int grow = row0 + r0 + r;
        float m  = mask[grow];
        float ws = g_wsum[grow];
        float dw = g_dwsum[grow];
        float c1 = fmaf(ws, m, -1.0f);
        float c2 = dw * m;
        u64 c1x = pk2(c1, c1);
        u64 c2x = pk2(c2, c2);
        u64 mx  = pk2(m, m);

        ulonglong2 ov;
        {
            u64 a2 = *(const u64*)&A2s[c0];
            u64 bb = *(const u64*)&bs[c0];
            u64 t;  FMA2(t, c1x, acc[r][2], acc[r][0]);   // G0 + c1*G1
            u64 t2; FMA2(t2, c2x, a2, bb);                 // c2*A2 + bias
            u64 s;  ADD2(s, t, t2);
            MUL2(ov.x, s, mx);
        }
        {
            u64 a2 = *(const u64*)&A2s[c0 + 2];
            u64 bb = *(const u64*)&bs[c0 + 2];
            u64 t;  FMA2(t, c1x, acc[r][3], acc[r][1]);
            u64 t2; FMA2(t2, c2x, a2, bb);
            u64 s;  ADD2(s, t, t2);
            MUL2(ov.y, s, mx);
        }
        *(ulonglong2*)&out[(size_t)grow * NO + c0] = ov;
    }
}

extern "C" void kernel_launch(void* const* d_in, const int* in_sizes, int n_in,
                              void* d_out, int out_size) {
    const float* x    = (const float*)d_in[0];
    const float* mask = (const float*)d_in[1];
    const float* A    = (const float*)d_in[2];
    const float* bias = (const float*)d_in[3];
    float* out = (float*)d_out;

    const int smem_bytes = (64 * 256 + 64 * 68 + 128 + 128) * sizeof(float);
    cudaFuncSetAttribute(gemm_kernel, cudaFuncAttributeMaxDynamicSharedMemorySize, smem_bytes);

    pairwise_kernel<<<NB * (NN / 64), 256>>>(x);
    gemm_kernel<<<(NB * NN) / GROWS, 256, smem_bytes>>>(x, mask, A, bias, out);
}

// round 4
// speedup vs baseline: 1.3932x; 1.3434x over previous
#include <cuda_runtime.h>
#include <cuda_bf16.h>
#include <cstdint>
#include <cstddef>

#define NB 32
#define NN 1024
#define NF 64
#define NO 128

typedef unsigned long long u64;
typedef uint32_t u32;

// Precomputed A as bf16 hi/lo in B-operand layout [n][k] (n=0..255, k=0..63)
__device__ __align__(16) __nv_bfloat16 Bhi_g[256 * 64];
__device__ __align__(16) __nv_bfloat16 Blo_g[256 * 64];

// ---------------------------------------------------------------------------
// smem layout (bytes). X/B tiles use padded 144B rows (128B data + 16B pad)
// so ldmatrix 8-row accesses are bank-conflict-free without swizzle.
// ---------------------------------------------------------------------------
#define OFF_COORD 0                         // float2 coords[1024] (8KB)
#define OFF_COEF  8192                      // c1s[128], c2s[128], ms[128]
#define OFF_RED   9728                      // redw[512], redd[512]
#define OFF_A2    13824                     // A2s[128]
#define OFF_BS    14336                     // bs[128]
#define OFF_XHI   15360                     // 128 rows x 144B
#define OFF_XLO   (OFF_XHI + 128 * 144)
#define OFF_BHI   (OFF_XLO + 128 * 144)     // 256 rows x 144B
#define OFF_BLO   (OFF_BHI + 256 * 144)
#define SMEM_TOTAL (OFF_BLO + 256 * 144)    // 125952 B

__device__ __forceinline__ u32 smem_u32(const void* p) {
    u32 a;
    asm("{ .reg .u64 t; cvta.to.shared.u64 t, %1; cvt.u32.u64 %0, t; }" : "=r"(a) : "l"(p));
    return a;
}
__device__ __forceinline__ float fast_exp2(float t) {
    float r; asm("ex2.approx.f32 %0, %1;" : "=f"(r) : "f"(t)); return r;
}
#define LDSM_X4(r0, r1, r2, r3, addr) \
    asm volatile("ldmatrix.sync.aligned.m8n8.x4.shared.b16 {%0,%1,%2,%3}, [%4];" \
                 : "=r"(r0), "=r"(r1), "=r"(r2), "=r"(r3) : "r"(addr))

__device__ __forceinline__ void mma16816(float* d, const u32* a, const u32* b) {
    asm volatile(
        "mma.sync.aligned.m16n8k16.row.col.f32.bf16.bf16.f32 "
        "{%0,%1,%2,%3}, {%4,%5,%6,%7}, {%8,%9}, {%0,%1,%2,%3};"
        : "+f"(d[0]), "+f"(d[1]), "+f"(d[2]), "+f"(d[3])
        : "r"(a[0]), "r"(a[1]), "r"(a[2]), "r"(a[3]), "r"(b[0]), "r"(b[1]));
}

// ---------------------------------------------------------------------------
// Prep: convert A -> Bhi/Blo bf16, layout [n][k]
//   n<128: A0[k][n];  n>=128: A1[k][n-128]
// ---------------------------------------------------------------------------
__global__ void prep_kernel(const float* __restrict__ A) {
    int idx = blockIdx.x * blockDim.x + threadIdx.x;   // 0..16383
    int n = idx >> 6, k = idx & 63;
    float a = (n < 128) ? A[k * 128 + n] : A[(64 + k) * 128 + (n - 128)];
    __nv_bfloat16 h = __float2bfloat16_rn(a);
    float r = a - __bfloat162float(h);
    Bhi_g[idx] = h;
    Blo_g[idx] = __float2bfloat16_rn(r);
}

// ---------------------------------------------------------------------------
// Fused kernel: per CTA, 128 rows of one batch.
// grid = 256, block = 512 (16 warps).
// Warp tile: 32 rows x (32 G0 cols + matching 32 G1 cols).
// ---------------------------------------------------------------------------
__global__ void __launch_bounds__(512, 1) fused_kernel(
    const float* __restrict__ x,
    const float* __restrict__ mask,
    const float* __restrict__ A,
    const float* __restrict__ bias,
    float* __restrict__ out)
{
    extern __shared__ __align__(1024) char sm[];
    const u32 sbase = smem_u32(sm);
    const int t = threadIdx.x;
    const int wid = t >> 5;
    const int lane = t & 31;

    const int b   = blockIdx.x >> 3;
    const int seg = blockIdx.x & 7;
    const int row0 = b * NN + seg * 128;

    float2* coords = (float2*)(sm + OFF_COORD);
    float* c1s = (float*)(sm + OFF_COEF);
    float* c2s = c1s + 128;
    float* ms  = c2s + 128;
    float* redw = (float*)(sm + OFF_RED);
    float* redd = redw + 512;
    float* A2s = (float*)(sm + OFF_A2);
    float* bs  = (float*)(sm + OFF_BS);

    // ---- loads ----
    // coords: whole batch
    for (int i = t; i < NN; i += 512)
        coords[i] = *(const float2*)(x + ((size_t)b * NN + i) * NF + (NF - 2));

    // x tile -> bf16 hi/lo into padded smem. thread: row=t>>2, 16 cols
    {
        int row = t >> 2;
        int cb  = (t & 3) * 16;
        const float* xr = x + (size_t)(row0 + row) * NF + cb;
        char* xh = sm + OFF_XHI + row * 144 + cb * 2;
        char* xl = sm + OFF_XLO + row * 144 + cb * 2;
        #pragma unroll
        for (int q = 0; q < 4; q++) {
            float4 v = *(const float4*)(xr + q * 4);
            __nv_bfloat16 h0 = __float2bfloat16_rn(v.x);
            __nv_bfloat16 h1 = __float2bfloat16_rn(v.y);
            __nv_bfloat16 h2 = __float2bfloat16_rn(v.z);
            __nv_bfloat16 h3 = __float2bfloat16_rn(v.w);
            __nv_bfloat16 l0 = __float2bfloat16_rn(v.x - __bfloat162float(h0));
            __nv_bfloat16 l1 = __float2bfloat16_rn(v.y - __bfloat162float(h1));
            __nv_bfloat16 l2 = __float2bfloat16_rn(v.z - __bfloat162float(h2));
            __nv_bfloat16 l3 = __float2bfloat16_rn(v.w - __bfloat162float(h3));
            u32 hi01 = ((u32)__bfloat16_as_ushort(h1) << 16) | __bfloat16_as_ushort(h0);
            u32 hi23 = ((u32)__bfloat16_as_ushort(h3) << 16) | __bfloat16_as_ushort(h2);
            u32 lo01 = ((u32)__bfloat16_as_ushort(l1) << 16) | __bfloat16_as_ushort(l0);
            u32 lo23 = ((u32)__bfloat16_as_ushort(l3) << 16) | __bfloat16_as_ushort(l2);
            *(u32*)(xh + q * 8)     = hi01;
            *(u32*)(xh + q * 8 + 4) = hi23;
            *(u32*)(xl + q * 8)     = lo01;
            *(u32*)(xl + q * 8 + 4) = lo23;
        }
    }

    // B tiles: bf16 globals -> padded smem rows
    {
        const uint4* bh = (const uint4*)Bhi_g;
        const uint4* bl = (const uint4*)Blo_g;
        for (int idx = t; idx < 2048; idx += 512) {        // 256 rows x 8 chunks
            int row = idx >> 3, q = idx & 7;
            char* dst_off = sm + row * 144 + q * 16;
            *(uint4*)(dst_off + OFF_BHI) = bh[idx];
            *(uint4*)(dst_off + OFF_BLO) = bl[idx];
        }
    }

    if (t < 128) {
        A2s[t] = A[128 * 128 + t];
        bs[t]  = bias[t];
    }
    __syncthreads();

    // ---- pairwise Gaussian sums ----
    {
        const int jloc = t & 127;
        const int quarter = t >> 7;
        const float2 cj = coords[seg * 128 + jloc];
        const float jx = cj.x, jy = cj.y;
        const float K = -14.4269504089f;   // -10 * log2(e)

        float ws0 = 0.f, ws1 = 0.f, dw0 = 0.f, dw1 = 0.f;
        const int i0 = quarter * 256;
        #pragma unroll 4
        for (int i = i0; i < i0 + 256; i += 2) {
            float2 c0 = coords[i];
            float2 c1 = coords[i + 1];
            float dx0 = c0.x - jx, dy0 = c0.y - jy;
            float d0 = fmaf(dy0, dy0, dx0 * dx0);
            float w0 = fast_exp2(d0 * K);
            ws0 += w0;
            dw0 = fmaf(d0, w0, dw0);
            float dx1 = c1.x - jx, dy1 = c1.y - jy;
            float d1 = fmaf(dy1, dy1, dx1 * dx1);
            float w1 = fast_exp2(d1 * K);
            ws1 += w1;
            dw1 = fmaf(d1, w1, dw1);
        }
        redw[quarter * 128 + jloc] = ws0 + ws1;
        redd[quarter * 128 + jloc] = dw0 + dw1;
    }
    __syncthreads();

    if (t < 128) {
        float ws = (redw[t] + redw[128 + t]) + (redw[256 + t] + redw[384 + t]);
        float dw = (redd[t] + redd[128 + t]) + (redd[256 + t] + redd[384 + t]);
        float m = mask[row0 + t];
        ms[t]  = m;
        c1s[t] = fmaf(ws, m, -1.0f);
        c2s[t] = dw * m;
    }

    // ---- MMA: 3-term bf16 split, warp tiles ----
    const int m0  = (wid & 3) * 32;     // warp rows
    const int c0w = (wid >> 2) * 32;    // warp G0 col base (G1 = +128)

    // ldmatrix per-thread address components
    const int g = lane >> 3, ri = lane & 7;
    const u32 arow = ri + ((g & 1) << 3);
    const u32 acol = (g >> 1) << 4;
    const u32 brow = ri + ((g >> 1) << 3);
    const u32 bcol = (g & 1) << 4;

    float acc[2][8][4];
    #pragma unroll
    for (int mt = 0; mt < 2; mt++)
        #pragma unroll
        for (int nb = 0; nb < 8; nb++)
            #pragma unroll
            for (int e = 0; e < 4; e++)
                acc[mt][nb][e] = 0.f;

    const u32 nbase[4] = { (u32)c0w, (u32)c0w + 16, (u32)c0w + 128, (u32)c0w + 144 };

    #pragma unroll
    for (int term = 0; term < 3; term++) {
        const u32 Xb = sbase + ((term == 2) ? OFF_XLO : OFF_XHI);
        const u32 Bb = sbase + ((term == 1) ? OFF_BLO : OFF_BHI);
        #pragma unroll
        for (int k = 0; k < 4; k++) {
            u32 af[2][4];
            #pragma unroll
            for (int mt = 0; mt < 2; mt++) {
                u32 addr = Xb + (m0 + mt * 16 + arow) * 144 + k * 32 + acol;
                LDSM_X4(af[mt][0], af[mt][1], af[mt][2], af[mt][3], addr);
            }
            u32 bf[8][2];
            #pragma unroll
            for (int p = 0; p < 4; p++) {
                u32 addr = Bb + (nbase[p] + brow) * 144 + k * 32 + bcol;
                LDSM_X4(bf[2 * p][0], bf[2 * p][1], bf[2 * p + 1][0], bf[2 * p + 1][1], addr);
            }
            #pragma unroll
            for (int nb = 0; nb < 8; nb++) {
                mma16816(acc[0][nb], af[0], bf[nb]);
                mma16816(acc[1][nb], af[1], bf[nb]);
            }
        }
    }
    __syncthreads();   // coefs published

    // ---- epilogue ----
    #pragma unroll
    for (int mt = 0; mt < 2; mt++) {
        const int r1 = m0 + mt * 16 + (lane >> 2);
        const int r2 = r1 + 8;
        const float m1 = ms[r1],  mA = ms[r2];
        const float c11 = c1s[r1], c12 = c1s[r2];
        const float c21 = c2s[r1], c22 = c2s[r2];
        #pragma unroll
        for (int nb = 0; nb < 4; nb++) {
            const int col = c0w + nb * 8 + (lane & 3) * 2;
            const float a20 = A2s[col], a21 = A2s[col + 1];
            const float b0 = bs[col],  b1 = bs[col + 1];
            const float* g0 = acc[mt][nb];
            const float* g1 = acc[mt][nb + 4];
            float2 o1, o2;
            o1.x = (fmaf(c11, g1[0], g0[0]) + fmaf(c21, a20, b0)) * m1;
            o1.y = (fmaf(c11, g1[1], g0[1]) + fmaf(c21, a21, b1)) * m1;
            o2.x = (fmaf(c12, g1[2], g0[2]) + fmaf(c22, a20, b0)) * mA;
            o2.y = (fmaf(c12, g1[3], g0[3]) + fmaf(c22, a21, b1)) * mA;
            *(float2*)(out + (size_t)(row0 + r1) * NO + col) = o1;
            *(float2*)(out + (size_t)(row0 + r2) * NO + col) = o2;
        }
    }
}

extern "C" void kernel_launch(void* const* d_in, const int* in_sizes, int n_in,
                              void* d_out, int out_size) {
    const float* x    = (const float*)d_in[0];
    const float* mask = (const float*)d_in[1];
    const float* A    = (const float*)d_in[2];
    const float* bias = (const float*)d_in[3];
    float* out = (float*)d_out;

    cudaFuncSetAttribute(fused_kernel, cudaFuncAttributeMaxDynamicSharedMemorySize, SMEM_TOTAL);

    prep_kernel<<<16, 1024>>>(A);
    fused_kernel<<<NB * 8, 512, SMEM_TOTAL>>>(x, mask, A, bias, out);
}